// round 5
// baseline (speedup 1.0000x reference)
#include <cuda_runtime.h>
#include <cstdint>

#define Bn 16
#define Cn 256
#define Ln 4096
#define Pn 100
#define Qn 20
#define TL 64              // l-tile
#define SROW 260           // 1040B rows: 16B-aligned, conflict-free LDS.128
#define NW 25              // warps per block (800 threads)
#define KP 4               // p per warp: p = w + 25k, k < 4 -> exactly covers 0..99
#define NTILES (Bn * (Ln / TL))   // 1024
#define GRID 148           // persistent blocks, 1/SM
#define NTHR (NW * 32)     // 800

__global__ void zero_cdf_kernel(float* out) {
    int i = blockIdx.x * 256 + threadIdx.x;
    if (i < Bn * Pn * Qn) out[i] = 0.0f;
}

__device__ __forceinline__ unsigned long long ffma2(unsigned long long a,
                                                    unsigned long long b,
                                                    unsigned long long c) {
    unsigned long long d;
    asm("fma.rn.f32x2 %0, %1, %2, %3;" : "=l"(d) : "l"(a), "l"(b), "l"(c));
    return d;
}
__device__ __forceinline__ void unpack2(unsigned long long v, float& x, float& y) {
    asm("mov.b64 {%0,%1}, %2;" : "=f"(x), "=f"(y) : "l"(v));
}

__global__ __launch_bounds__(NTHR, 1)
void csf_persistent_kernel(const float* __restrict__ X,
                           const float* __restrict__ proj,
                           const float* __restrict__ minv,
                           const float* __restrict__ maxv,
                           float* __restrict__ out) {
    extern __shared__ float sm[];
    float* Xe  = sm;                          // [32][SROW]  even l
    float* Xo  = sm + 32 * SROW;              // [32][SROW]  odd l
    float* pst = sm + 64 * SROW;              // [Pn][Cn]    no padding
    float* thr = pst + Pn * Cn;               // [Pn*Qn]

    const int tid  = threadIdx.x;
    const int w    = tid >> 5;
    const int lane = tid & 31;

    // ---- One-time staging: projections + thresholds ----
    for (int i = tid; i < Pn * Cn / 4; i += NTHR)
        ((float4*)pst)[i] = ((const float4*)proj)[i];
    for (int i = tid; i < Pn * Qn; i += NTHR) {
        int p = i / Qn, q = i % Qn;
        float f = (float)(q + 1) / (float)(Qn + 1);
        thr[i] = minv[p] + (maxv[p] - minv[p]) * f;
    }

    const float* xa = Xe + lane * SROW;   // l = l0 + 2*lane
    const float* xb = Xo + lane * SROW;   // l = l0 + 2*lane + 1
    const float* ps0 = pst + (w +  0) * Cn;
    const float* ps1 = pst + (w + 25) * Cn;
    const float* ps2 = pst + (w + 50) * Cn;
    const float* ps3 = pst + (w + 75) * Cn;

    for (int t = blockIdx.x; t < NTILES; t += GRID) {
        const int b  = t >> 6;
        const int l0 = (t & 63) * TL;

        // ---- Load X tile, split even/odd l (coalesced LDG.128 over l) ----
        {
            const float* Xb = X + (size_t)b * Cn * Ln + l0;
            #pragma unroll
            for (int j = 0; j < 6; j++) {
                int s = j * NTHR + tid;          // float4 slot
                if (s < Cn * TL / 4) {
                    int c  = s >> 4;
                    int l4 = (s & 15) * 4;
                    float4 v = *(const float4*)(Xb + (size_t)c * Ln + l4);
                    int r = l4 >> 1;
                    Xe[(r + 0) * SROW + c] = v.x;
                    Xo[(r + 0) * SROW + c] = v.y;
                    Xe[(r + 1) * SROW + c] = v.z;
                    Xo[(r + 1) * SROW + c] = v.w;
                }
            }
        }
        __syncthreads();

        // ---- Compute: each warp owns exactly 4 real p ----
        unsigned long long acc0[KP], acc1[KP];
        #pragma unroll
        for (int k = 0; k < KP; k++) { acc0[k] = 0ull; acc1[k] = 0ull; }

        #pragma unroll 4
        for (int c = 0; c < Cn; c += 4) {
            ulonglong2 x0 = *(const ulonglong2*)(xa + c);
            ulonglong2 x1 = *(const ulonglong2*)(xb + c);
            ulonglong2 p0 = *(const ulonglong2*)(ps0 + c);
            ulonglong2 p1 = *(const ulonglong2*)(ps1 + c);
            ulonglong2 p2 = *(const ulonglong2*)(ps2 + c);
            ulonglong2 p3 = *(const ulonglong2*)(ps3 + c);
            acc0[0] = ffma2(p0.x, x0.x, acc0[0]); acc0[0] = ffma2(p0.y, x0.y, acc0[0]);
            acc1[0] = ffma2(p0.x, x1.x, acc1[0]); acc1[0] = ffma2(p0.y, x1.y, acc1[0]);
            acc0[1] = ffma2(p1.x, x0.x, acc0[1]); acc0[1] = ffma2(p1.y, x0.y, acc0[1]);
            acc1[1] = ffma2(p1.x, x1.x, acc1[1]); acc1[1] = ffma2(p1.y, x1.y, acc1[1]);
            acc0[2] = ffma2(p2.x, x0.x, acc0[2]); acc0[2] = ffma2(p2.y, x0.y, acc0[2]);
            acc1[2] = ffma2(p2.x, x1.x, acc1[2]); acc1[2] = ffma2(p2.y, x1.y, acc1[2]);
            acc0[3] = ffma2(p3.x, x0.x, acc0[3]); acc0[3] = ffma2(p3.y, x0.y, acc0[3]);
            acc1[3] = ffma2(p3.x, x1.x, acc1[3]); acc1[3] = ffma2(p3.y, x1.y, acc1[3]);
        }

        // ---- Epilogue: set stores + cdf counts (no divergence: all p real) ----
        float* cdfb = out + b * (Pn * Qn);
        float* setb = out + Bn * Pn * Qn + (size_t)b * Pn * Qn * Ln;

        #pragma unroll
        for (int k = 0; k < KP; k++) {
            const int p = w + 25 * k;
            float e0, o0, e1, o1;
            unpack2(acc0[k], e0, o0);
            unpack2(acc1[k], e1, o1);
            float a0 = e0 + o0;   // l = l0 + 2*lane
            float a1 = e1 + o1;   // l = l0 + 2*lane + 1

            float2* dst = (float2*)(setb + (size_t)p * Qn * Ln + l0) + lane;
            const float* th = thr + p * Qn;

            #pragma unroll
            for (int qq = 0; qq < Qn; qq += 4) {
                unsigned packed = 0;
                #pragma unroll
                for (int j = 0; j < 4; j++) {
                    float tt = th[qq + j];
                    unsigned s0 = (a0 < tt) ? 1u : 0u;
                    unsigned s1 = (a1 < tt) ? 1u : 0u;
                    dst[(size_t)(qq + j) * (Ln / 2)] = make_float2((float)s0, (float)s1);
                    packed += (s0 + s1) << (8 * j);    // per-byte sum <= 64
                }
                unsigned r = __reduce_add_sync(0xffffffffu, packed);
                if (lane < 4) {
                    float v = (float)((r >> (8 * lane)) & 255u) * (1.0f / 4096.0f);
                    atomicAdd(cdfb + p * Qn + qq + lane, v);   // exact dyadic
                }
            }
        }
        __syncthreads();   // all warps done with Xs before next tile overwrites
    }
}

extern "C" void kernel_launch(void* const* d_in, const int* in_sizes, int n_in,
                              void* d_out, int out_size) {
    const float* X    = (const float*)d_in[0];
    const float* proj = (const float*)d_in[1];
    const float* minv = (const float*)d_in[2];
    const float* maxv = (const float*)d_in[3];
    float* out = (float*)d_out;

    zero_cdf_kernel<<<(Bn * Pn * Qn + 255) / 256, 256>>>(out);

    const int smem = (64 * SROW + Pn * Cn + Pn * Qn) * (int)sizeof(float);
    cudaFuncSetAttribute(csf_persistent_kernel,
                         cudaFuncAttributeMaxDynamicSharedMemorySize, smem);
    csf_persistent_kernel<<<GRID, NTHR, smem>>>(X, proj, minv, maxv, out);
}